// round 7
// baseline (speedup 1.0000x reference)
#include <cuda_runtime.h>
#include <cstdint>

// Problem constants (fixed by dataset).
#define U_C  100000
#define I_C  50000
#define N_C  150000
#define ROWS_TOT (N_C + U_C + I_C)       // 300000
#define CAP  24                          // bucket capacity; perm = 57.6MB -> L2-resident
#define OVF_CAP 65536

#define TPB 256
#define D64 64
#define SEPT 4                           // scatter: edges per thread (MLP)

__device__ int  d_curs[ROWS_TOT];
__device__ int2 d_perm[(size_t)ROWS_TOT * CAP];
__device__ int  d_ovf_count;
__device__ int4 d_ovf[OVF_CAP];          // {key, col, val_bits, 0}

// ---------------- build: single bucket-scatter pass, MLP=SEPT ----------------
__global__ void __launch_bounds__(TPB) scatter_all(
        const int* __restrict__ gr, const int* __restrict__ gc, const float* __restrict__ gv,
        const int* __restrict__ ur, const int* __restrict__ uc, const float* __restrict__ uv,
        const int* __restrict__ ir, const int* __restrict__ ic, const float* __restrict__ iv,
        int EG, int EU, int EI, int N_, int U_) {
    const int ET = EG + EU + EI;
    long long base   = (long long)blockIdx.x * TPB + threadIdx.x;
    long long stride = (long long)gridDim.x * TPB;

    int  key[SEPT], col[SEPT]; float val[SEPT]; bool ok[SEPT];

    // Phase 1: resolve edge descriptors (independent loads).
    #pragma unroll
    for (int k = 0; k < SEPT; k++) {
        long long e = base + (long long)k * stride;
        ok[k] = (e < ET);
        if (ok[k]) {
            int ei = (int)e;
            if (ei < EG) {
                key[k] = __ldcs(gr + ei);            col[k] = __ldcs(gc + ei);  val[k] = __ldcs(gv + ei);
            } else if (ei < EG + EU) {
                int kk = ei - EG;
                key[k] = N_ + __ldcs(ur + kk);       col[k] = __ldcs(uc + kk);  val[k] = __ldcs(uv + kk);
            } else {
                int kk = ei - EG - EU;
                key[k] = N_ + U_ + __ldcs(ir + kk);  col[k] = __ldcs(ic + kk);  val[k] = __ldcs(iv + kk);
            }
        }
    }

    // Phase 2: independent cursor atomics (MLP = SEPT over 318cyc latency).
    int pos[SEPT];
    #pragma unroll
    for (int k = 0; k < SEPT; k++) {
        if (ok[k]) pos[k] = atomicAdd(&d_curs[key[k]], 1);
    }

    // Phase 3: bucket stores (independent).
    #pragma unroll
    for (int k = 0; k < SEPT; k++) {
        if (ok[k]) {
            if (pos[k] < CAP) {
                d_perm[(size_t)key[k] * CAP + pos[k]] = make_int2(col[k], __float_as_int(val[k]));
            } else {
                int o = atomicAdd(&d_ovf_count, 1);
                if (o < OVF_CAP) d_ovf[o] = make_int4(key[k], col[k], __float_as_int(val[k]), 0);
            }
        }
    }
}

// ---------------- fused main: all 300K rows in one launch ----------------
__global__ void __launch_bounds__(TPB) csr_spmm_fused(const float* __restrict__ user_emb,
                                                      const float* __restrict__ item_emb,
                                                      float* __restrict__ out,
                                                      int N_, int U_, int I_) {
    int tid  = blockIdx.x * TPB + threadIdx.x;
    int key  = tid >> 4;
    int lane = tid & 15;
    if (key >= N_ + U_ + I_) return;

    const float* src0;
    const float* src1;
    int U_split;
    if (key < N_) {                    // graph: concat(user, item) source
        src0 = user_emb; src1 = item_emb; U_split = U_;
    } else if (key < N_ + U_) {        // user SpMM
        src0 = user_emb; src1 = user_emb; U_split = 0x7FFFFFFF;
    } else {                           // item SpMM
        src0 = item_emb; src1 = item_emb; U_split = 0x7FFFFFFF;
    }

    int deg = min(d_curs[key], CAP);
    const int2* bucket = d_perm + (size_t)key * CAP;

    float4 acc = make_float4(0.f, 0.f, 0.f, 0.f);

    int j = 0;
    for (; j + 4 <= deg; j += 4) {
        int2 e0 = __ldcs(bucket + j);
        int2 e1 = __ldcs(bucket + j + 1);
        int2 e2 = __ldcs(bucket + j + 2);
        int2 e3 = __ldcs(bucket + j + 3);
        const float* p0 = (e0.x < U_split) ? src0 + (long long)e0.x * D64 : src1 + (long long)(e0.x - U_split) * D64;
        const float* p1 = (e1.x < U_split) ? src0 + (long long)e1.x * D64 : src1 + (long long)(e1.x - U_split) * D64;
        const float* p2 = (e2.x < U_split) ? src0 + (long long)e2.x * D64 : src1 + (long long)(e2.x - U_split) * D64;
        const float* p3 = (e3.x < U_split) ? src0 + (long long)e3.x * D64 : src1 + (long long)(e3.x - U_split) * D64;
        float4 x0 = reinterpret_cast<const float4*>(p0)[lane];
        float4 x1 = reinterpret_cast<const float4*>(p1)[lane];
        float4 x2 = reinterpret_cast<const float4*>(p2)[lane];
        float4 x3 = reinterpret_cast<const float4*>(p3)[lane];
        float v0 = __int_as_float(e0.y), v1 = __int_as_float(e1.y);
        float v2 = __int_as_float(e2.y), v3 = __int_as_float(e3.y);
        acc.x = fmaf(v0, x0.x, acc.x); acc.y = fmaf(v0, x0.y, acc.y); acc.z = fmaf(v0, x0.z, acc.z); acc.w = fmaf(v0, x0.w, acc.w);
        acc.x = fmaf(v1, x1.x, acc.x); acc.y = fmaf(v1, x1.y, acc.y); acc.z = fmaf(v1, x1.z, acc.z); acc.w = fmaf(v1, x1.w, acc.w);
        acc.x = fmaf(v2, x2.x, acc.x); acc.y = fmaf(v2, x2.y, acc.y); acc.z = fmaf(v2, x2.z, acc.z); acc.w = fmaf(v2, x2.w, acc.w);
        acc.x = fmaf(v3, x3.x, acc.x); acc.y = fmaf(v3, x3.y, acc.y); acc.z = fmaf(v3, x3.z, acc.z); acc.w = fmaf(v3, x3.w, acc.w);
    }
    for (; j < deg; j++) {
        int2 e = __ldcs(bucket + j);
        const float* p = (e.x < U_split) ? src0 + (long long)e.x * D64 : src1 + (long long)(e.x - U_split) * D64;
        float4 x = reinterpret_cast<const float4*>(p)[lane];
        float v = __int_as_float(e.y);
        acc.x = fmaf(v, x.x, acc.x); acc.y = fmaf(v, x.y, acc.y);
        acc.z = fmaf(v, x.z, acc.z); acc.w = fmaf(v, x.w, acc.w);
    }

    __stcs(reinterpret_cast<float4*>(out + (long long)key * D64) + lane, acc);
}

// ---------------- overflow fixup (exactness; small) ----------------
__global__ void __launch_bounds__(TPB) fixup(const float* __restrict__ user_emb,
                                             const float* __restrict__ item_emb,
                                             float* __restrict__ out,
                                             int N_, int U_) {
    int n = min(d_ovf_count, OVF_CAP);
    long long total = (long long)n * 16;
    for (long long t = blockIdx.x * (long long)TPB + threadIdx.x; t < total;
         t += (long long)gridDim.x * TPB) {
        int idx  = (int)(t >> 4);
        int lane = (int)(t & 15);
        int4 e = d_ovf[idx];
        int key = e.x, c = e.y;
        float v = __int_as_float(e.z);
        const float* src;
        if (key < N_)            src = (c < U_) ? user_emb + (long long)c * D64
                                                : item_emb + (long long)(c - U_) * D64;
        else if (key < N_ + U_)  src = user_emb + (long long)c * D64;
        else                     src = item_emb + (long long)c * D64;
        float4 x = reinterpret_cast<const float4*>(src)[lane];
        x.x *= v; x.y *= v; x.z *= v; x.w *= v;
        float4* d = reinterpret_cast<float4*>(out + (long long)key * D64) + lane;
        asm volatile("red.global.add.v4.f32 [%0], {%1,%2,%3,%4};"
                     :: "l"(d), "f"(x.x), "f"(x.y), "f"(x.z), "f"(x.w)
                     : "memory");
    }
}

extern "C" void kernel_launch(void* const* d_in, const int* in_sizes, int n_in,
                              void* d_out, int out_size) {
    const float* user_emb = (const float*)d_in[0];
    const float* item_emb = (const float*)d_in[1];
    const int*   g_rows = (const int*)d_in[2];
    const int*   g_cols = (const int*)d_in[3];
    const float* g_vals = (const float*)d_in[4];
    const int*   u_rows = (const int*)d_in[5];
    const int*   u_cols = (const int*)d_in[6];
    const float* u_vals = (const float*)d_in[7];
    const int*   i_rows = (const int*)d_in[8];
    const int*   i_cols = (const int*)d_in[9];
    const float* i_vals = (const float*)d_in[10];

    float* out = (float*)d_out;

    const int U_ = in_sizes[0] / D64;   // 100000
    const int I_ = in_sizes[1] / D64;   // 50000
    const int N_ = U_ + I_;
    const int EG = in_sizes[2];
    const int EU = in_sizes[5];
    const int EI = in_sizes[8];
    const int ET = EG + EU + EI;
    const int ROWS = N_ + U_ + I_;

    // Zero cursors + overflow counter.
    void* curs_ptr = nullptr;
    cudaGetSymbolAddress(&curs_ptr, d_curs);
    cudaMemsetAsync(curs_ptr, 0, (size_t)ROWS * sizeof(int), 0);
    void* ovf_ptr = nullptr;
    cudaGetSymbolAddress(&ovf_ptr, d_ovf_count);
    cudaMemsetAsync(ovf_ptr, 0, sizeof(int), 0);

    // Build (MLP=SEPT edges per thread).
    {
        long long threads_needed = ((long long)ET + SEPT - 1) / SEPT;
        int blocks = (int)((threads_needed + TPB - 1) / TPB);
        scatter_all<<<blocks, TPB>>>(g_rows, g_cols, g_vals,
                                     u_rows, u_cols, u_vals,
                                     i_rows, i_cols, i_vals,
                                     EG, EU, EI, N_, U_);
    }

    // Fused main over all rows.
    {
        long long threads = (long long)ROWS * 16;
        int blocks = (int)((threads + TPB - 1) / TPB);
        csr_spmm_fused<<<blocks, TPB>>>(user_emb, item_emb, out, N_, U_, I_);
    }

    // Exact fixup for bucket overflow.
    fixup<<<256, TPB>>>(user_emb, item_emb, out, N_, U_);
}

// round 8
// speedup vs baseline: 1.1125x; 1.1125x over previous
#include <cuda_runtime.h>
#include <cstdint>

// Problem constants (fixed by dataset).
#define U_C  100000
#define I_C  50000
#define N_C  150000
#define ROWS_TOT (N_C + U_C + I_C)       // 300000
#define CAP  24                          // perm = 57.6MB -> L2-resident
#define OVF_CAP 65536

#define TPB 256
#define D64 64

__device__ int  d_curs[ROWS_TOT];
__device__ int2 d_perm[(size_t)ROWS_TOT * CAP];
__device__ int  d_ovf_count;
__device__ int4 d_ovf[OVF_CAP];          // {key, col, val_bits, 0}

// ---------------- build: one list per launch (SEPT=1; measured best) --------
__global__ void __launch_bounds__(TPB) scatter_list(const int* __restrict__ rows,
                                                    const int* __restrict__ cols,
                                                    const float* __restrict__ vals,
                                                    int E, int key_base) {
    int e = blockIdx.x * TPB + threadIdx.x;
    if (e >= E) return;
    int key = key_base + __ldcs(rows + e);
    int c   = __ldcs(cols + e);
    float v = __ldcs(vals + e);
    int pos = atomicAdd(&d_curs[key], 1);
    if (pos < CAP) {
        d_perm[(size_t)key * CAP + pos] = make_int2(c, __float_as_int(v));
    } else {
        int o = atomicAdd(&d_ovf_count, 1);
        if (o < OVF_CAP) d_ovf[o] = make_int4(key, c, __float_as_int(v), 0);
    }
}

// ---------------- main: key range [row_base, row_base+n_rows) ---------------
// 16 threads per destination row; register accumulation; streaming store.
__global__ void __launch_bounds__(TPB) csr_spmm_range(const float* __restrict__ user_emb,
                                                      const float* __restrict__ item_emb,
                                                      float* __restrict__ out,
                                                      int row_base, int n_rows,
                                                      int N_, int U_) {
    int tid  = blockIdx.x * TPB + threadIdx.x;
    int rr   = tid >> 4;
    int lane = tid & 15;
    if (rr >= n_rows) return;
    int key = row_base + rr;

    const float* src0;
    const float* src1;
    int U_split;
    if (key < N_) {                    // graph: concat(user, item) source
        src0 = user_emb; src1 = item_emb; U_split = U_;
    } else if (key < N_ + U_) {        // user SpMM
        src0 = user_emb; src1 = user_emb; U_split = 0x7FFFFFFF;
    } else {                           // item SpMM
        src0 = item_emb; src1 = item_emb; U_split = 0x7FFFFFFF;
    }

    int deg = min(d_curs[key], CAP);
    const int2* bucket = d_perm + (size_t)key * CAP;

    float4 acc = make_float4(0.f, 0.f, 0.f, 0.f);

    int j = 0;
    for (; j + 4 <= deg; j += 4) {
        int2 e0 = __ldcs(bucket + j);
        int2 e1 = __ldcs(bucket + j + 1);
        int2 e2 = __ldcs(bucket + j + 2);
        int2 e3 = __ldcs(bucket + j + 3);
        const float* p0 = (e0.x < U_split) ? src0 + (long long)e0.x * D64 : src1 + (long long)(e0.x - U_split) * D64;
        const float* p1 = (e1.x < U_split) ? src0 + (long long)e1.x * D64 : src1 + (long long)(e1.x - U_split) * D64;
        const float* p2 = (e2.x < U_split) ? src0 + (long long)e2.x * D64 : src1 + (long long)(e2.x - U_split) * D64;
        const float* p3 = (e3.x < U_split) ? src0 + (long long)e3.x * D64 : src1 + (long long)(e3.x - U_split) * D64;
        float4 x0 = reinterpret_cast<const float4*>(p0)[lane];
        float4 x1 = reinterpret_cast<const float4*>(p1)[lane];
        float4 x2 = reinterpret_cast<const float4*>(p2)[lane];
        float4 x3 = reinterpret_cast<const float4*>(p3)[lane];
        float v0 = __int_as_float(e0.y), v1 = __int_as_float(e1.y);
        float v2 = __int_as_float(e2.y), v3 = __int_as_float(e3.y);
        acc.x = fmaf(v0, x0.x, acc.x); acc.y = fmaf(v0, x0.y, acc.y); acc.z = fmaf(v0, x0.z, acc.z); acc.w = fmaf(v0, x0.w, acc.w);
        acc.x = fmaf(v1, x1.x, acc.x); acc.y = fmaf(v1, x1.y, acc.y); acc.z = fmaf(v1, x1.z, acc.z); acc.w = fmaf(v1, x1.w, acc.w);
        acc.x = fmaf(v2, x2.x, acc.x); acc.y = fmaf(v2, x2.y, acc.y); acc.z = fmaf(v2, x2.z, acc.z); acc.w = fmaf(v2, x2.w, acc.w);
        acc.x = fmaf(v3, x3.x, acc.x); acc.y = fmaf(v3, x3.y, acc.y); acc.z = fmaf(v3, x3.z, acc.z); acc.w = fmaf(v3, x3.w, acc.w);
    }
    for (; j < deg; j++) {
        int2 e = __ldcs(bucket + j);
        const float* p = (e.x < U_split) ? src0 + (long long)e.x * D64 : src1 + (long long)(e.x - U_split) * D64;
        float4 x = reinterpret_cast<const float4*>(p)[lane];
        float v = __int_as_float(e.y);
        acc.x = fmaf(v, x.x, acc.x); acc.y = fmaf(v, x.y, acc.y);
        acc.z = fmaf(v, x.z, acc.z); acc.w = fmaf(v, x.w, acc.w);
    }

    __stcs(reinterpret_cast<float4*>(out + (long long)key * D64) + lane, acc);
}

// ---------------- overflow fixup (exactness; small) ----------------
__global__ void __launch_bounds__(TPB) fixup(const float* __restrict__ user_emb,
                                             const float* __restrict__ item_emb,
                                             float* __restrict__ out,
                                             int N_, int U_) {
    int n = min(d_ovf_count, OVF_CAP);
    long long total = (long long)n * 16;
    for (long long t = blockIdx.x * (long long)TPB + threadIdx.x; t < total;
         t += (long long)gridDim.x * TPB) {
        int idx  = (int)(t >> 4);
        int lane = (int)(t & 15);
        int4 e = d_ovf[idx];
        int key = e.x, c = e.y;
        float v = __int_as_float(e.z);
        const float* src;
        if (key < N_)            src = (c < U_) ? user_emb + (long long)c * D64
                                                : item_emb + (long long)(c - U_) * D64;
        else if (key < N_ + U_)  src = user_emb + (long long)c * D64;
        else                     src = item_emb + (long long)c * D64;
        float4 x = reinterpret_cast<const float4*>(src)[lane];
        x.x *= v; x.y *= v; x.z *= v; x.w *= v;
        float4* d = reinterpret_cast<float4*>(out + (long long)key * D64) + lane;
        asm volatile("red.global.add.v4.f32 [%0], {%1,%2,%3,%4};"
                     :: "l"(d), "f"(x.x), "f"(x.y), "f"(x.z), "f"(x.w)
                     : "memory");
    }
}

extern "C" void kernel_launch(void* const* d_in, const int* in_sizes, int n_in,
                              void* d_out, int out_size) {
    const float* user_emb = (const float*)d_in[0];
    const float* item_emb = (const float*)d_in[1];
    const int*   g_rows = (const int*)d_in[2];
    const int*   g_cols = (const int*)d_in[3];
    const float* g_vals = (const float*)d_in[4];
    const int*   u_rows = (const int*)d_in[5];
    const int*   u_cols = (const int*)d_in[6];
    const float* u_vals = (const float*)d_in[7];
    const int*   i_rows = (const int*)d_in[8];
    const int*   i_cols = (const int*)d_in[9];
    const float* i_vals = (const float*)d_in[10];

    float* out = (float*)d_out;

    const int U_ = in_sizes[0] / D64;   // 100000
    const int I_ = in_sizes[1] / D64;   // 50000
    const int N_ = U_ + I_;
    const int EG = in_sizes[2];
    const int EU = in_sizes[5];
    const int EI = in_sizes[8];
    const int ROWS = N_ + U_ + I_;

    // Zero cursors + overflow counter (ordered before the fork).
    void* curs_ptr = nullptr;
    cudaGetSymbolAddress(&curs_ptr, d_curs);
    cudaMemsetAsync(curs_ptr, 0, (size_t)ROWS * sizeof(int), 0);
    void* ovf_ptr = nullptr;
    cudaGetSymbolAddress(&ovf_ptr, d_ovf_count);
    cudaMemsetAsync(ovf_ptr, 0, sizeof(int), 0);

    // Fork a second stream into the capture: user/item chain runs concurrent
    // with the graph chain (scatter is latency-bound, main is BW-bound ->
    // overlapping them fills LTS).
    cudaStream_t s2;
    cudaStreamCreateWithFlags(&s2, cudaStreamNonBlocking);
    cudaEvent_t evFork, evJoin;
    cudaEventCreateWithFlags(&evFork, cudaEventDisableTiming);
    cudaEventCreateWithFlags(&evJoin, cudaEventDisableTiming);

    cudaEventRecord(evFork, 0);
    cudaStreamWaitEvent(s2, evFork, 0);

    // ---- chain B on s2: user + item ----
    scatter_list<<<(EU + TPB - 1) / TPB, TPB, 0, s2>>>(u_rows, u_cols, u_vals, EU, N_);
    scatter_list<<<(EI + TPB - 1) / TPB, TPB, 0, s2>>>(i_rows, i_cols, i_vals, EI, N_ + U_);
    {
        int n_rows = U_ + I_;
        int blocks = (n_rows * 16 + TPB - 1) / TPB;
        csr_spmm_range<<<blocks, TPB, 0, s2>>>(user_emb, item_emb, out, N_, n_rows, N_, U_);
    }
    cudaEventRecord(evJoin, s2);

    // ---- chain A on stream 0: graph ----
    scatter_list<<<(EG + TPB - 1) / TPB, TPB>>>(g_rows, g_cols, g_vals, EG, 0);
    {
        int blocks = (N_ * 16 + TPB - 1) / TPB;
        csr_spmm_range<<<blocks, TPB>>>(user_emb, item_emb, out, 0, N_, N_, U_);
    }

    // ---- join, then exact overflow fixup ----
    cudaStreamWaitEvent(0, evJoin, 0);
    fixup<<<256, TPB>>>(user_emb, item_emb, out, N_, U_);

    cudaEventDestroy(evFork);
    cudaEventDestroy(evJoin);
    cudaStreamDestroy(s2);
}